// round 1
// baseline (speedup 1.0000x reference)
#include <cuda_runtime.h>

// Problem constants
#define SLEN 512
#define BSZ  64
#define ID   512
#define HID  512
#define NG   2048   // 4*H
#define NBLK 128    // persistent blocks (must all be co-resident; 128 <= 148 SMs)

// Scratch (device globals: allocation-free)
static __device__ float    g_Xg[134217728];        // (D, S, B, 4H) = 2*512*64*2048
static __device__ float    g_h[2][2][HID][BSZ];    // [buf][d][h][b]
static __device__ unsigned g_bar;

__global__ void init_kernel() { g_bar = 0u; }

// ---------------------------------------------------------------------------
// Phase 1: Xg[d, s, b, :] = X[s,b,:] @ W[d]^T + Wb[d] + Rb[d]
// M = S*B = 32768, N = 4H = 2048, K = I = 512. NT GEMM, fp32.
// ---------------------------------------------------------------------------
__global__ __launch_bounds__(256) void gemm_xw(const float* __restrict__ X,
                                               const float* __restrict__ W,
                                               const float* __restrict__ Bb) {
    const int d    = blockIdx.z;
    const int col0 = blockIdx.x * 128;
    const int row0 = blockIdx.y * 128;
    const float* Wd = W + (size_t)d * NG * ID;
    float* C = g_Xg + (size_t)d * SLEN * BSZ * NG;

    __shared__ float As[16][132];  // [k][m], pad 132 keeps 16B alignment
    __shared__ float Bs[16][132];  // [k][n]

    const int tid = threadIdx.x;
    const int tx = tid & 15;       // n-tile
    const int ty = tid >> 4;       // m-tile
    const int lrow = tid >> 1;     // 0..127
    const int lk4  = (tid & 1) * 8;

    float acc[8][8];
#pragma unroll
    for (int i = 0; i < 8; i++)
#pragma unroll
        for (int j = 0; j < 8; j++) acc[i][j] = 0.f;

    for (int kk = 0; kk < ID; kk += 16) {
        float4 a0 = *(const float4*)(X  + (size_t)(row0 + lrow) * ID + kk + lk4);
        float4 a1 = *(const float4*)(X  + (size_t)(row0 + lrow) * ID + kk + lk4 + 4);
        float4 b0 = *(const float4*)(Wd + (size_t)(col0 + lrow) * ID + kk + lk4);
        float4 b1 = *(const float4*)(Wd + (size_t)(col0 + lrow) * ID + kk + lk4 + 4);
        __syncthreads();
        As[lk4 + 0][lrow] = a0.x; As[lk4 + 1][lrow] = a0.y;
        As[lk4 + 2][lrow] = a0.z; As[lk4 + 3][lrow] = a0.w;
        As[lk4 + 4][lrow] = a1.x; As[lk4 + 5][lrow] = a1.y;
        As[lk4 + 6][lrow] = a1.z; As[lk4 + 7][lrow] = a1.w;
        Bs[lk4 + 0][lrow] = b0.x; Bs[lk4 + 1][lrow] = b0.y;
        Bs[lk4 + 2][lrow] = b0.z; Bs[lk4 + 3][lrow] = b0.w;
        Bs[lk4 + 4][lrow] = b1.x; Bs[lk4 + 5][lrow] = b1.y;
        Bs[lk4 + 6][lrow] = b1.z; Bs[lk4 + 7][lrow] = b1.w;
        __syncthreads();
#pragma unroll 4
        for (int k = 0; k < 16; k++) {
            float4 af0 = *(const float4*)&As[k][ty * 8];
            float4 af1 = *(const float4*)&As[k][ty * 8 + 4];
            float4 bf0 = *(const float4*)&Bs[k][tx * 8];
            float4 bf1 = *(const float4*)&Bs[k][tx * 8 + 4];
            float a[8] = {af0.x, af0.y, af0.z, af0.w, af1.x, af1.y, af1.z, af1.w};
            float b[8] = {bf0.x, bf0.y, bf0.z, bf0.w, bf1.x, bf1.y, bf1.z, bf1.w};
#pragma unroll
            for (int i = 0; i < 8; i++)
#pragma unroll
                for (int j = 0; j < 8; j++) acc[i][j] += a[i] * b[j];
        }
    }

    float bias[8];
#pragma unroll
    for (int j = 0; j < 8; j++) {
        int c = col0 + tx * 8 + j;
        bias[j] = Bb[(size_t)d * 4096 + c] + Bb[(size_t)d * 4096 + 2048 + c];
    }
#pragma unroll
    for (int i = 0; i < 8; i++) {
        float4 v0 = make_float4(acc[i][0] + bias[0], acc[i][1] + bias[1],
                                acc[i][2] + bias[2], acc[i][3] + bias[3]);
        float4 v1 = make_float4(acc[i][4] + bias[4], acc[i][5] + bias[5],
                                acc[i][6] + bias[6], acc[i][7] + bias[7]);
        size_t r = (size_t)(row0 + ty * 8 + i) * NG + col0 + tx * 8;
        *(float4*)(C + r)     = v0;
        *(float4*)(C + r + 4) = v1;
    }
}

// ---------------------------------------------------------------------------
// Phase 2: persistent bidirectional recurrence. One grid barrier per step.
// Block layout: blk = d*64 + hchunk; owns 8 h-indices (all 4 gates) x 64 batch.
// ---------------------------------------------------------------------------
__device__ __forceinline__ void grid_barrier(unsigned target) {
    __syncthreads();
    if (threadIdx.x == 0) {
        __threadfence();
        atomicAdd(&g_bar, 1u);
        unsigned v;
        do {
            asm volatile("ld.acquire.gpu.u32 %0, [%1];" : "=r"(v) : "l"(&g_bar) : "memory");
        } while (v < target);
    }
    __syncthreads();
}

__device__ __forceinline__ float sigmoidf_(float x) {
    return 1.f / (1.f + __expf(-x));
}

__global__ __launch_bounds__(256) void lstm_rec(const float* __restrict__ R,
                                                const int*   __restrict__ seq,
                                                const float* __restrict__ h0,
                                                const float* __restrict__ c0,
                                                const float* __restrict__ P,
                                                float* __restrict__ out) {
    const int blk = blockIdx.x;
    const int d   = blk >> 6;
    const int hb  = (blk & 63) * 8;
    const int tid = threadIdx.x;

    __shared__ float hT[64][64];       // [k][b] chunk of h
    __shared__ float Rs[32][65];       // [j][k] chunk of R (pad 65: conflict-free)
    __shared__ float accs[4][8][65];   // [gate][hl][b] (pad 65)
    __shared__ float cs[8][64], c0s[8][64], h0s[8][64];
    __shared__ float Ps[3][8];
    __shared__ int   slen[BSZ];

    if (tid < BSZ) slen[tid] = seq[tid];
    if (tid < 24) {
        int w = tid / 8, hl = tid % 8;
        Ps[w][hl] = P[(size_t)d * 1536 + w * 512 + hb + hl];
    }
    for (int p = tid; p < 512; p += 256) {
        int hl = p >> 6, b = p & 63;
        size_t idx = ((size_t)d * BSZ + b) * HID + hb + hl;
        float hv = h0[idx], cv = c0[idx];
        h0s[hl][b] = hv; c0s[hl][b] = cv; cs[hl][b] = cv;
        g_h[0][d][hb + hl][b] = hv;
    }

    unsigned target = NBLK;
    grid_barrier(target); target += NBLK;   // all initial h visible

    const int j    = tid & 31;              // gate*8 + hl
    const int bg   = tid >> 5;              // batch group (warp id)
    const int gate = j >> 3;
    const int hl0  = j & 7;
    const int colg = gate * 512 + hb + hl0; // row of R (and column of Xg)

    float* Yh = out + 33554432;             // S*D*B*H
    float* Yc = Yh + 65536;                 // D*B*H

    for (int s = 0; s < SLEN; ++s) {
        const int t   = d ? (SLEN - 1 - s) : s;
        const int cur = s & 1, nxt = cur ^ 1;

        // Prefetch Xg (includes Wb+Rb) before the barrier: hides DRAM latency.
        float acc[8];
        const float* xg = g_Xg + (((size_t)d * SLEN + t) * BSZ) * NG + colg;
#pragma unroll
        for (int i = 0; i < 8; i++) acc[i] = xg[(size_t)(bg * 8 + i) * NG];

        grid_barrier(target); target += NBLK;   // h(t) ready

        // acc[b_local] += sum_k h[b][k] * R[colg][k]
        for (int kk = 0; kk < 8; kk++) {
            __syncthreads();
#pragma unroll
            for (int r = 0; r < 4; r++) {
                int idx = tid + r * 256;
                int row = idx >> 4, c4 = idx & 15;
                float4 v = *(const float4*)&g_h[cur][d][kk * 64 + row][c4 * 4];
                *(float4*)&hT[row][c4 * 4] = v;
            }
            {
                int j2 = tid >> 3, kq = tid & 7;
                const float* rp = R + ((size_t)d * NG + (j2 >> 3) * 512 + hb + (j2 & 7)) * ID
                                  + kk * 64 + kq * 8;
                float4 v0 = *(const float4*)rp;
                float4 v1 = *(const float4*)(rp + 4);
                Rs[j2][kq * 8 + 0] = v0.x; Rs[j2][kq * 8 + 1] = v0.y;
                Rs[j2][kq * 8 + 2] = v0.z; Rs[j2][kq * 8 + 3] = v0.w;
                Rs[j2][kq * 8 + 4] = v1.x; Rs[j2][kq * 8 + 5] = v1.y;
                Rs[j2][kq * 8 + 6] = v1.z; Rs[j2][kq * 8 + 7] = v1.w;
            }
            __syncthreads();
#pragma unroll 8
            for (int k = 0; k < 64; k++) {
                float rv = Rs[j][k];
                float4 ha = *(const float4*)&hT[k][bg * 8];
                float4 hc = *(const float4*)&hT[k][bg * 8 + 4];
                acc[0] += rv * ha.x; acc[1] += rv * ha.y;
                acc[2] += rv * ha.z; acc[3] += rv * ha.w;
                acc[4] += rv * hc.x; acc[5] += rv * hc.y;
                acc[6] += rv * hc.z; acc[7] += rv * hc.w;
            }
        }
#pragma unroll
        for (int i = 0; i < 8; i++) accs[gate][hl0][bg * 8 + i] = acc[i];
        __syncthreads();

        // Elementwise LSTM cell + peephole + mask, write Y and next h.
        for (int p = tid; p < 512; p += 256) {
            int hl = p >> 6, b = p & 63;
            float gi = accs[0][hl][b];
            float go = accs[1][hl][b];
            float gf = accs[2][hl][b];
            float gg = accs[3][hl][b];
            float c  = cs[hl][b];
            float iv = sigmoidf_(gi + Ps[0][hl] * c);
            float fv = sigmoidf_(gf + Ps[1][hl] * c);
            float ct = tanhf(gg);
            float cn = fv * c + iv * ct;
            float ov = sigmoidf_(go + Ps[2][hl] * cn);
            float hn = ov * tanhf(cn);
            if (t >= slen[b]) { hn = h0s[hl][b]; cn = c0s[hl][b]; }
            cs[hl][b] = cn;
            g_h[nxt][d][hb + hl][b] = hn;
            out[(((size_t)t * 2 + d) * BSZ + b) * HID + hb + hl] = hn;
            if (s == SLEN - 1) {
                size_t fi = ((size_t)d * BSZ + b) * HID + hb + hl;
                Yh[fi] = hn;
                Yc[fi] = cn;
            }
        }
    }
}

// ---------------------------------------------------------------------------
extern "C" void kernel_launch(void* const* d_in, const int* in_sizes, int n_in,
                              void* d_out, int out_size) {
    const float* X   = (const float*)d_in[0];
    const float* W   = (const float*)d_in[1];
    const float* R   = (const float*)d_in[2];
    const float* Bb  = (const float*)d_in[3];
    const int*   sl  = (const int*)  d_in[4];
    const float* h0  = (const float*)d_in[5];
    const float* c0  = (const float*)d_in[6];
    const float* P   = (const float*)d_in[7];
    float* out = (float*)d_out;

    init_kernel<<<1, 1>>>();
    gemm_xw<<<dim3(16, 256, 2), 256>>>(X, W, Bb);
    lstm_rec<<<NBLK, 256>>>(R, sl, h0, c0, P, out);
}

// round 3
// speedup vs baseline: 1.2357x; 1.2357x over previous
#include <cuda_runtime.h>
#include <cstdint>

// Problem constants
#define SLEN 512
#define BSZ  64
#define ID   512
#define HID  512
#define NG   2048   // 4*H
#define NBLK 128    // persistent blocks for phase 2

// Scratch (device globals: allocation-free)
static __device__ float    g_Xg[134217728];        // (D, S, B, 4H)
static __device__ float    g_h[2][2][HID][BSZ];    // [buf][d][h][b]
static __device__ unsigned g_bar;

__global__ void init_kernel() { g_bar = 0u; }

__device__ __forceinline__ uint32_t f2tf32(float x) {
    uint32_t r;
    asm("cvt.rna.tf32.f32 %0, %1;" : "=r"(r) : "f"(x));
    return r;
}

// ===========================================================================
// Phase 1: Xg[d, r, :] = X[r,:] @ W[d]^T + Wb[d] + Rb[d]
// tf32 mma.sync.m16n8k8. M=32768, N=2048, K=512.
// Block tile 128x128, 8 warps (4m x 2n), warp tile 32x64, K-chunk 32.
// ===========================================================================
#define PADK 36

__global__ __launch_bounds__(256) void gemm_xw_tc(const float* __restrict__ X,
                                                  const float* __restrict__ W,
                                                  const float* __restrict__ Bb) {
    __shared__ float As[128][PADK];   // [m][k], tf32 bits
    __shared__ float Bs[128][PADK];   // [n][k], tf32 bits
    __shared__ float biass[128];

    const int tid  = threadIdx.x;
    const int wid  = tid >> 5, lane = tid & 31;
    const int d    = blockIdx.z;
    const int col0 = blockIdx.x * 128;
    const int row0 = blockIdx.y * 128;
    const float* Am = X + (size_t)row0 * ID;
    const float* Bm = W + ((size_t)d * NG + col0) * ID;
    float* C = g_Xg + (size_t)d * SLEN * BSZ * NG;

    if (tid < 128) {
        biass[tid] = Bb[(size_t)d * 4096 + col0 + tid]
                   + Bb[(size_t)d * 4096 + 2048 + col0 + tid];
    }

    const int wm  = (wid & 3) * 32;   // warp m offset in tile
    const int wn  = (wid >> 2) * 64;  // warp n offset in tile
    const int grp = lane >> 2;        // 0..7
    const int thr = lane & 3;         // 0..3

    const int lrow = tid >> 3;        // 0..31 (row group for loads)
    const int lkp  = (tid & 7) * 4;   // k position (float4)

    float cr[2][8][4];
#pragma unroll
    for (int mt = 0; mt < 2; mt++)
#pragma unroll
        for (int nt = 0; nt < 8; nt++)
#pragma unroll
            for (int q = 0; q < 4; q++) cr[mt][nt][q] = 0.f;

    // Prefetch chunk 0
    float4 ra[4], rb[4];
#pragma unroll
    for (int i = 0; i < 4; i++) {
        int r = lrow + i * 32;
        ra[i] = *(const float4*)(Am + (size_t)r * ID + lkp);
        rb[i] = *(const float4*)(Bm + (size_t)r * ID + lkp);
    }

#pragma unroll 1
    for (int c = 0; c < 16; c++) {
        __syncthreads();   // previous chunk's compute done reading smem
#pragma unroll
        for (int i = 0; i < 4; i++) {
            int r = lrow + i * 32;
            float4 ca, cb;
            ca.x = __uint_as_float(f2tf32(ra[i].x));
            ca.y = __uint_as_float(f2tf32(ra[i].y));
            ca.z = __uint_as_float(f2tf32(ra[i].z));
            ca.w = __uint_as_float(f2tf32(ra[i].w));
            cb.x = __uint_as_float(f2tf32(rb[i].x));
            cb.y = __uint_as_float(f2tf32(rb[i].y));
            cb.z = __uint_as_float(f2tf32(rb[i].z));
            cb.w = __uint_as_float(f2tf32(rb[i].w));
            *(float4*)&As[r][lkp] = ca;
            *(float4*)&Bs[r][lkp] = cb;
        }
        __syncthreads();

        if (c < 15) {     // issue next chunk's global loads (overlap with MMA)
            const int kk = (c + 1) * 32;
#pragma unroll
            for (int i = 0; i < 4; i++) {
                int r = lrow + i * 32;
                ra[i] = *(const float4*)(Am + (size_t)r * ID + kk + lkp);
                rb[i] = *(const float4*)(Bm + (size_t)r * ID + kk + lkp);
            }
        }

#pragma unroll
        for (int ks = 0; ks < 4; ks++) {
            const int k0 = ks * 8;
            uint32_t af[2][4];
#pragma unroll
            for (int mt = 0; mt < 2; mt++) {
                const int mr = wm + mt * 16;
                af[mt][0] = __float_as_uint(As[mr + grp][k0 + thr]);
                af[mt][1] = __float_as_uint(As[mr + grp + 8][k0 + thr]);
                af[mt][2] = __float_as_uint(As[mr + grp][k0 + thr + 4]);
                af[mt][3] = __float_as_uint(As[mr + grp + 8][k0 + thr + 4]);
            }
#pragma unroll
            for (int nt = 0; nt < 8; nt++) {
                const int nr = wn + nt * 8;
                uint32_t b0 = __float_as_uint(Bs[nr + grp][k0 + thr]);
                uint32_t b1 = __float_as_uint(Bs[nr + grp][k0 + thr + 4]);
#pragma unroll
                for (int mt = 0; mt < 2; mt++) {
                    asm volatile(
                        "mma.sync.aligned.m16n8k8.row.col.f32.tf32.tf32.f32 "
                        "{%0,%1,%2,%3}, {%4,%5,%6,%7}, {%8,%9}, {%0,%1,%2,%3};"
                        : "+f"(cr[mt][nt][0]), "+f"(cr[mt][nt][1]),
                          "+f"(cr[mt][nt][2]), "+f"(cr[mt][nt][3])
                        : "r"(af[mt][0]), "r"(af[mt][1]), "r"(af[mt][2]), "r"(af[mt][3]),
                          "r"(b0), "r"(b1));
                }
            }
        }
    }

    // Epilogue: C(m, col) += bias
#pragma unroll
    for (int mt = 0; mt < 2; mt++) {
        const int m0 = row0 + wm + mt * 16 + grp;
#pragma unroll
        for (int nt = 0; nt < 8; nt++) {
            const int cl = wn + nt * 8 + 2 * thr;    // col within tile
            float2 v0 = make_float2(cr[mt][nt][0] + biass[cl],
                                    cr[mt][nt][1] + biass[cl + 1]);
            float2 v1 = make_float2(cr[mt][nt][2] + biass[cl],
                                    cr[mt][nt][3] + biass[cl + 1]);
            *(float2*)(C + (size_t)m0 * NG + col0 + cl)       = v0;
            *(float2*)(C + (size_t)(m0 + 8) * NG + col0 + cl) = v1;
        }
    }
}

// ===========================================================================
// Phase 2: persistent bidirectional recurrence (unchanged from R1, proven).
// ===========================================================================
__device__ __forceinline__ void grid_barrier(unsigned target) {
    __syncthreads();
    if (threadIdx.x == 0) {
        __threadfence();
        atomicAdd(&g_bar, 1u);
        unsigned v;
        do {
            asm volatile("ld.acquire.gpu.u32 %0, [%1];" : "=r"(v) : "l"(&g_bar) : "memory");
        } while (v < target);
    }
    __syncthreads();
}

__device__ __forceinline__ float sigmoidf_(float x) {
    return 1.f / (1.f + __expf(-x));
}

__global__ __launch_bounds__(256) void lstm_rec(const float* __restrict__ R,
                                                const int*   __restrict__ seq,
                                                const float* __restrict__ h0,
                                                const float* __restrict__ c0,
                                                const float* __restrict__ P,
                                                float* __restrict__ out) {
    const int blk = blockIdx.x;
    const int d   = blk >> 6;
    const int hb  = (blk & 63) * 8;
    const int tid = threadIdx.x;

    __shared__ float hT[64][64];
    __shared__ float Rs[32][65];
    __shared__ float accs[4][8][65];
    __shared__ float cs[8][64], c0s[8][64], h0s[8][64];
    __shared__ float Ps[3][8];
    __shared__ int   slen[BSZ];

    if (tid < BSZ) slen[tid] = seq[tid];
    if (tid < 24) {
        int w = tid / 8, hl = tid % 8;
        Ps[w][hl] = P[(size_t)d * 1536 + w * 512 + hb + hl];
    }
    for (int p = tid; p < 512; p += 256) {
        int hl = p >> 6, b = p & 63;
        size_t idx = ((size_t)d * BSZ + b) * HID + hb + hl;
        float hv = h0[idx], cv = c0[idx];
        h0s[hl][b] = hv; c0s[hl][b] = cv; cs[hl][b] = cv;
        g_h[0][d][hb + hl][b] = hv;
    }

    unsigned target = NBLK;
    grid_barrier(target); target += NBLK;

    const int j    = tid & 31;
    const int bg   = tid >> 5;
    const int gate = j >> 3;
    const int hl0  = j & 7;
    const int colg = gate * 512 + hb + hl0;

    float* Yh = out + 33554432;
    float* Yc = Yh + 65536;

    for (int s = 0; s < SLEN; ++s) {
        const int t   = d ? (SLEN - 1 - s) : s;
        const int cur = s & 1, nxt = cur ^ 1;

        float acc[8];
        const float* xg = g_Xg + (((size_t)d * SLEN + t) * BSZ) * NG + colg;
#pragma unroll
        for (int i = 0; i < 8; i++) acc[i] = xg[(size_t)(bg * 8 + i) * NG];

        grid_barrier(target); target += NBLK;

        for (int kk = 0; kk < 8; kk++) {
            __syncthreads();
#pragma unroll
            for (int r = 0; r < 4; r++) {
                int idx = tid + r * 256;
                int row = idx >> 4, c4 = idx & 15;
                float4 v = *(const float4*)&g_h[cur][d][kk * 64 + row][c4 * 4];
                *(float4*)&hT[row][c4 * 4] = v;
            }
            {
                int j2 = tid >> 3, kq = tid & 7;
                const float* rp = R + ((size_t)d * NG + (j2 >> 3) * 512 + hb + (j2 & 7)) * ID
                                  + kk * 64 + kq * 8;
                float4 v0 = *(const float4*)rp;
                float4 v1 = *(const float4*)(rp + 4);
                Rs[j2][kq * 8 + 0] = v0.x; Rs[j2][kq * 8 + 1] = v0.y;
                Rs[j2][kq * 8 + 2] = v0.z; Rs[j2][kq * 8 + 3] = v0.w;
                Rs[j2][kq * 8 + 4] = v1.x; Rs[j2][kq * 8 + 5] = v1.y;
                Rs[j2][kq * 8 + 6] = v1.z; Rs[j2][kq * 8 + 7] = v1.w;
            }
            __syncthreads();
#pragma unroll 8
            for (int k = 0; k < 64; k++) {
                float rv = Rs[j][k];
                float4 ha = *(const float4*)&hT[k][bg * 8];
                float4 hc = *(const float4*)&hT[k][bg * 8 + 4];
                acc[0] += rv * ha.x; acc[1] += rv * ha.y;
                acc[2] += rv * ha.z; acc[3] += rv * ha.w;
                acc[4] += rv * hc.x; acc[5] += rv * hc.y;
                acc[6] += rv * hc.z; acc[7] += rv * hc.w;
            }
        }
#pragma unroll
        for (int i = 0; i < 8; i++) accs[gate][hl0][bg * 8 + i] = acc[i];
        __syncthreads();

        for (int p = tid; p < 512; p += 256) {
            int hl = p >> 6, b = p & 63;
            float gi = accs[0][hl][b];
            float go = accs[1][hl][b];
            float gf = accs[2][hl][b];
            float gg = accs[3][hl][b];
            float c  = cs[hl][b];
            float iv = sigmoidf_(gi + Ps[0][hl] * c);
            float fv = sigmoidf_(gf + Ps[1][hl] * c);
            float ct = tanhf(gg);
            float cn = fv * c + iv * ct;
            float ov = sigmoidf_(go + Ps[2][hl] * cn);
            float hn = ov * tanhf(cn);
            if (t >= slen[b]) { hn = h0s[hl][b]; cn = c0s[hl][b]; }
            cs[hl][b] = cn;
            g_h[nxt][d][hb + hl][b] = hn;
            out[(((size_t)t * 2 + d) * BSZ + b) * HID + hb + hl] = hn;
            if (s == SLEN - 1) {
                size_t fi = ((size_t)d * BSZ + b) * HID + hb + hl;
                Yh[fi] = hn;
                Yc[fi] = cn;
            }
        }
    }
}

// ---------------------------------------------------------------------------
extern "C" void kernel_launch(void* const* d_in, const int* in_sizes, int n_in,
                              void* d_out, int out_size) {
    const float* X   = (const float*)d_in[0];
    const float* W   = (const float*)d_in[1];
    const float* R   = (const float*)d_in[2];
    const float* Bb  = (const float*)d_in[3];
    const int*   sl  = (const int*)  d_in[4];
    const float* h0  = (const float*)d_in[5];
    const float* c0  = (const float*)d_in[6];
    const float* P   = (const float*)d_in[7];
    float* out = (float*)d_out;

    init_kernel<<<1, 1>>>();
    gemm_xw_tc<<<dim3(16, 256, 2), 256>>>(X, W, Bb);
    lstm_rec<<<NBLK, 256>>>(R, sl, h0, c0, P, out);
}

// round 4
// speedup vs baseline: 2.0187x; 1.6336x over previous
#include <cuda_runtime.h>
#include <cstdint>

// Problem constants
#define SLEN 512
#define BSZ  64
#define ID   512
#define HID  512
#define NG   2048   // 4*H
#define NBLK 128    // persistent blocks for phase 2

// Scratch (device globals: allocation-free)
static __device__ float    g_Xg[134217728];        // (D, S, B, 4H)
static __device__ float    g_h[2][2][HID][BSZ];    // [buf][d][h][b]
static __device__ unsigned g_bar;

__device__ __forceinline__ uint32_t f2tf32(float x) {
    uint32_t r;
    asm("cvt.rna.tf32.f32 %0, %1;" : "=r"(r) : "f"(x));
    return r;
}

// ===========================================================================
// Phase 1: Xg[d, r, :] = X[r,:] @ W[d]^T + Wb[d] + Rb[d]
// tf32 mma.sync.m16n8k8. Block tile 128x128, 8 warps, warp tile 32x64.
// ===========================================================================
#define PADK 36

__global__ __launch_bounds__(256) void gemm_xw_tc(const float* __restrict__ X,
                                                  const float* __restrict__ W,
                                                  const float* __restrict__ Bb) {
    __shared__ float As[128][PADK];
    __shared__ float Bs[128][PADK];
    __shared__ float biass[128];

    const int tid  = threadIdx.x;
    const int wid  = tid >> 5, lane = tid & 31;
    const int d    = blockIdx.z;
    const int col0 = blockIdx.x * 128;
    const int row0 = blockIdx.y * 128;
    const float* Am = X + (size_t)row0 * ID;
    const float* Bm = W + ((size_t)d * NG + col0) * ID;
    float* C = g_Xg + (size_t)d * SLEN * BSZ * NG;

    // Reset the phase-2 grid barrier (gemm runs strictly before lstm_rec).
    if (blockIdx.x == 0 && blockIdx.y == 0 && blockIdx.z == 0 && tid == 0)
        g_bar = 0u;

    if (tid < 128) {
        biass[tid] = Bb[(size_t)d * 4096 + col0 + tid]
                   + Bb[(size_t)d * 4096 + 2048 + col0 + tid];
    }

    const int wm  = (wid & 3) * 32;
    const int wn  = (wid >> 2) * 64;
    const int grp = lane >> 2;
    const int thr = lane & 3;

    const int lrow = tid >> 3;
    const int lkp  = (tid & 7) * 4;

    float cr[2][8][4];
#pragma unroll
    for (int mt = 0; mt < 2; mt++)
#pragma unroll
        for (int nt = 0; nt < 8; nt++)
#pragma unroll
            for (int q = 0; q < 4; q++) cr[mt][nt][q] = 0.f;

    float4 ra[4], rb[4];
#pragma unroll
    for (int i = 0; i < 4; i++) {
        int r = lrow + i * 32;
        ra[i] = *(const float4*)(Am + (size_t)r * ID + lkp);
        rb[i] = *(const float4*)(Bm + (size_t)r * ID + lkp);
    }

#pragma unroll 1
    for (int c = 0; c < 16; c++) {
        __syncthreads();
#pragma unroll
        for (int i = 0; i < 4; i++) {
            int r = lrow + i * 32;
            float4 ca, cb;
            ca.x = __uint_as_float(f2tf32(ra[i].x));
            ca.y = __uint_as_float(f2tf32(ra[i].y));
            ca.z = __uint_as_float(f2tf32(ra[i].z));
            ca.w = __uint_as_float(f2tf32(ra[i].w));
            cb.x = __uint_as_float(f2tf32(rb[i].x));
            cb.y = __uint_as_float(f2tf32(rb[i].y));
            cb.z = __uint_as_float(f2tf32(rb[i].z));
            cb.w = __uint_as_float(f2tf32(rb[i].w));
            *(float4*)&As[r][lkp] = ca;
            *(float4*)&Bs[r][lkp] = cb;
        }
        __syncthreads();

        if (c < 15) {
            const int kk = (c + 1) * 32;
#pragma unroll
            for (int i = 0; i < 4; i++) {
                int r = lrow + i * 32;
                ra[i] = *(const float4*)(Am + (size_t)r * ID + kk + lkp);
                rb[i] = *(const float4*)(Bm + (size_t)r * ID + kk + lkp);
            }
        }

#pragma unroll
        for (int ks = 0; ks < 4; ks++) {
            const int k0 = ks * 8;
            uint32_t af[2][4];
#pragma unroll
            for (int mt = 0; mt < 2; mt++) {
                const int mr = wm + mt * 16;
                af[mt][0] = __float_as_uint(As[mr + grp][k0 + thr]);
                af[mt][1] = __float_as_uint(As[mr + grp + 8][k0 + thr]);
                af[mt][2] = __float_as_uint(As[mr + grp][k0 + thr + 4]);
                af[mt][3] = __float_as_uint(As[mr + grp + 8][k0 + thr + 4]);
            }
#pragma unroll
            for (int nt = 0; nt < 8; nt++) {
                const int nr = wn + nt * 8;
                uint32_t b0 = __float_as_uint(Bs[nr + grp][k0 + thr]);
                uint32_t b1 = __float_as_uint(Bs[nr + grp][k0 + thr + 4]);
#pragma unroll
                for (int mt = 0; mt < 2; mt++) {
                    asm volatile(
                        "mma.sync.aligned.m16n8k8.row.col.f32.tf32.tf32.f32 "
                        "{%0,%1,%2,%3}, {%4,%5,%6,%7}, {%8,%9}, {%0,%1,%2,%3};"
                        : "+f"(cr[mt][nt][0]), "+f"(cr[mt][nt][1]),
                          "+f"(cr[mt][nt][2]), "+f"(cr[mt][nt][3])
                        : "r"(af[mt][0]), "r"(af[mt][1]), "r"(af[mt][2]), "r"(af[mt][3]),
                          "r"(b0), "r"(b1));
                }
            }
        }
    }

#pragma unroll
    for (int mt = 0; mt < 2; mt++) {
        const int m0 = row0 + wm + mt * 16 + grp;
#pragma unroll
        for (int nt = 0; nt < 8; nt++) {
            const int cl = wn + nt * 8 + 2 * thr;
            float2 v0 = make_float2(cr[mt][nt][0] + biass[cl],
                                    cr[mt][nt][1] + biass[cl + 1]);
            float2 v1 = make_float2(cr[mt][nt][2] + biass[cl],
                                    cr[mt][nt][3] + biass[cl + 1]);
            *(float2*)(C + (size_t)m0 * NG + col0 + cl)       = v0;
            *(float2*)(C + (size_t)(m0 + 8) * NG + col0 + cl) = v1;
        }
    }
}

// ===========================================================================
// Phase 2: persistent bidirectional recurrence, tf32 mma.sync.
// Block = (d, 8 h-idx): gates G[64b][32] = h[64b][512] @ R_blk^T + Xg.
// R fragments register-resident (128 regs/thread); h staged tf32 in smem.
// ===========================================================================
__device__ __forceinline__ void grid_barrier(unsigned target) {
    __syncthreads();
    if (threadIdx.x == 0) {
        __threadfence();
        atomicAdd(&g_bar, 1u);
        unsigned v;
        do {
            asm volatile("ld.acquire.gpu.u32 %0, [%1];" : "=r"(v) : "l"(&g_bar) : "memory");
        } while (v < target);
    }
    __syncthreads();
}

__device__ __forceinline__ float sigmoidf_(float x) {
    return 1.f / (1.f + __expf(-x));
}

#define HS_STRIDE 72
#define HS_BYTES  (512 * HS_STRIDE * 4)

__global__ __launch_bounds__(256, 1) void lstm_rec(const float* __restrict__ R,
                                                   const int*   __restrict__ seq,
                                                   const float* __restrict__ h0,
                                                   const float* __restrict__ c0,
                                                   const float* __restrict__ P,
                                                   float* __restrict__ out) {
    extern __shared__ float hs[];            // [512][HS_STRIDE] tf32 h
    __shared__ float accs[4][8][65];         // [gate][hl][b]
    __shared__ float xgs[4][64][9];          // [gate][b][hl]
    __shared__ float cs[8][64], c0s[8][64], h0s[8][64];
    __shared__ float Ps[3][8];
    __shared__ int   slen[BSZ];

    const int blk = blockIdx.x;
    const int d   = blk >> 6;
    const int hb  = (blk & 63) * 8;
    const int tid = threadIdx.x;
    const int wid = tid >> 5, lane = tid & 31;
    const int grp = lane >> 2, thr = lane & 3;
    const int nt  = wid & 3;                 // gate index this warp computes
    const int m0  = (wid >> 2) * 32;         // first of 2 m16 tiles (m0, m0+16)

    // Preload R fragments (tf32) — constant across all steps.
    uint32_t Rb[128];
    {
        const float* Rrow = R + ((size_t)d * NG + nt * 512 + hb + grp) * HID;
#pragma unroll
        for (int ks = 0; ks < 64; ks++) {
            Rb[2 * ks]     = f2tf32(Rrow[ks * 8 + thr]);
            Rb[2 * ks + 1] = f2tf32(Rrow[ks * 8 + thr + 4]);
        }
    }

    if (tid < BSZ) slen[tid] = seq[tid];
    if (tid < 24) {
        int w = tid / 8, hl = tid % 8;
        Ps[w][hl] = P[(size_t)d * 1536 + w * 512 + hb + hl];
    }
    for (int p = tid; p < 512; p += 256) {
        int hl = p >> 6, b = p & 63;
        size_t idx = ((size_t)d * BSZ + b) * HID + hb + hl;
        float hv = h0[idx], cv = c0[idx];
        h0s[hl][b] = hv; c0s[hl][b] = cv; cs[hl][b] = cv;
        g_h[0][d][hb + hl][b] = hv;
    }

    unsigned target = NBLK;
    grid_barrier(target); target += NBLK;    // initial h visible everywhere

    float* Yh = out + 33554432;
    float* Yc = Yh + 65536;

    const int xm = tid >> 2, xg4 = tid & 3;  // Xg stage mapping

    for (int s = 0; s < SLEN; ++s) {
        const int t   = d ? (SLEN - 1 - s) : s;
        const int cur = s & 1, nxt = cur ^ 1;

        // Prefetch this block's Xg tile (before barrier: hides latency)
        const float* xp = g_Xg + (((size_t)d * SLEN + t) * BSZ + xm) * NG + xg4 * 512 + hb;
        float4 xv0 = *(const float4*)xp;
        float4 xv1 = *(const float4*)(xp + 4);

        grid_barrier(target); target += NBLK;   // h(t) ready

        // Stage Xg into smem (scalar stores; conflict-free: stride 9)
        xgs[xg4][xm][0] = xv0.x; xgs[xg4][xm][1] = xv0.y;
        xgs[xg4][xm][2] = xv0.z; xgs[xg4][xm][3] = xv0.w;
        xgs[xg4][xm][4] = xv1.x; xgs[xg4][xm][5] = xv1.y;
        xgs[xg4][xm][6] = xv1.z; xgs[xg4][xm][7] = xv1.w;

        // Stage h(t) (full 512 x 64, tf32-converted) into hs
#pragma unroll
        for (int i = 0; i < 32; i++) {
            int idx = tid + i * 256;
            int k = idx >> 4, b4 = (idx & 15) * 4;
            float4 v = *(const float4*)&g_h[cur][d][k][b4];
            float4 cv;
            cv.x = __uint_as_float(f2tf32(v.x));
            cv.y = __uint_as_float(f2tf32(v.y));
            cv.z = __uint_as_float(f2tf32(v.z));
            cv.w = __uint_as_float(f2tf32(v.w));
            *(float4*)&hs[k * HS_STRIDE + b4] = cv;
        }
        __syncthreads();

        // MMA: G = h @ R^T.  Warp: nt fixed, m tiles {m0, m0+16}.
        float acc[2][4];
#pragma unroll
        for (int mtf = 0; mtf < 2; mtf++)
#pragma unroll
            for (int q = 0; q < 4; q++) acc[mtf][q] = 0.f;

#pragma unroll
        for (int ks = 0; ks < 64; ks++) {
            const int r0 = (ks * 8 + thr) * HS_STRIDE;
            const int r4 = (ks * 8 + thr + 4) * HS_STRIDE;
            uint32_t b0 = Rb[2 * ks], b1 = Rb[2 * ks + 1];
#pragma unroll
            for (int mtf = 0; mtf < 2; mtf++) {
                const int mc = m0 + mtf * 16 + grp;
                uint32_t a0 = __float_as_uint(hs[r0 + mc]);
                uint32_t a1 = __float_as_uint(hs[r0 + mc + 8]);
                uint32_t a2 = __float_as_uint(hs[r4 + mc]);
                uint32_t a3 = __float_as_uint(hs[r4 + mc + 8]);
                asm volatile(
                    "mma.sync.aligned.m16n8k8.row.col.f32.tf32.tf32.f32 "
                    "{%0,%1,%2,%3}, {%4,%5,%6,%7}, {%8,%9}, {%0,%1,%2,%3};"
                    : "+f"(acc[mtf][0]), "+f"(acc[mtf][1]),
                      "+f"(acc[mtf][2]), "+f"(acc[mtf][3])
                    : "r"(a0), "r"(a1), "r"(a2), "r"(a3), "r"(b0), "r"(b1));
            }
        }

        // Exchange: fragments -> accs[gate][hl][b]
#pragma unroll
        for (int mtf = 0; mtf < 2; mtf++) {
            const int m = m0 + mtf * 16 + grp;
            accs[nt][2 * thr]    [m]     = acc[mtf][0];
            accs[nt][2 * thr + 1][m]     = acc[mtf][1];
            accs[nt][2 * thr]    [m + 8] = acc[mtf][2];
            accs[nt][2 * thr + 1][m + 8] = acc[mtf][3];
        }
        __syncthreads();

        // Elementwise LSTM cell + peephole + mask
        for (int p = tid; p < 512; p += 256) {
            int hl = p >> 6, b = p & 63;
            float gi = accs[0][hl][b] + xgs[0][b][hl];
            float go = accs[1][hl][b] + xgs[1][b][hl];
            float gf = accs[2][hl][b] + xgs[2][b][hl];
            float gg = accs[3][hl][b] + xgs[3][b][hl];
            float c  = cs[hl][b];
            float iv = sigmoidf_(gi + Ps[0][hl] * c);
            float fv = sigmoidf_(gf + Ps[1][hl] * c);
            float ct = tanhf(gg);
            float cn = fv * c + iv * ct;
            float ov = sigmoidf_(go + Ps[2][hl] * cn);
            float hn = ov * tanhf(cn);
            if (t >= slen[b]) { hn = h0s[hl][b]; cn = c0s[hl][b]; }
            cs[hl][b] = cn;
            g_h[nxt][d][hb + hl][b] = hn;
            out[(((size_t)t * 2 + d) * BSZ + b) * HID + hb + hl] = hn;
            if (s == SLEN - 1) {
                size_t fi = ((size_t)d * BSZ + b) * HID + hb + hl;
                Yh[fi] = hn;
                Yc[fi] = cn;
            }
        }
    }
}

// ---------------------------------------------------------------------------
extern "C" void kernel_launch(void* const* d_in, const int* in_sizes, int n_in,
                              void* d_out, int out_size) {
    const float* X   = (const float*)d_in[0];
    const float* W   = (const float*)d_in[1];
    const float* R   = (const float*)d_in[2];
    const float* Bb  = (const float*)d_in[3];
    const int*   sl  = (const int*)  d_in[4];
    const float* h0  = (const float*)d_in[5];
    const float* c0  = (const float*)d_in[6];
    const float* P   = (const float*)d_in[7];
    float* out = (float*)d_out;

    static int configured = 0;
    if (!configured) {
        cudaFuncSetAttribute(lstm_rec, cudaFuncAttributeMaxDynamicSharedMemorySize,
                             HS_BYTES);
        configured = 1;
    }

    gemm_xw_tc<<<dim3(16, 256, 2), 256>>>(X, W, Bb);
    lstm_rec<<<NBLK, 256, HS_BYTES>>>(R, sl, h0, c0, P, out);
}

// round 5
// speedup vs baseline: 2.7848x; 1.3795x over previous
#include <cuda_runtime.h>
#include <cstdint>

// Problem constants
#define SLEN 512
#define BSZ  64
#define ID   512
#define HID  512
#define NG   2048   // 4*H
#define NBLK 128    // persistent blocks for phase 2

// Scratch (device globals: allocation-free)
static __device__ float    g_Xg[134217728];        // (D, S, B, 4H)
static __device__ float    g_h[2][2][HID][BSZ];    // [buf][d][h][b]
static __device__ unsigned g_bar;

__device__ __forceinline__ uint32_t f2tf32(float x) {
    uint32_t r;
    asm("cvt.rna.tf32.f32 %0, %1;" : "=r"(r) : "f"(x));
    return r;
}

// ===========================================================================
// Phase 1: Xg[d, r, :] = X[r,:] @ W[d]^T + Wb[d] + Rb[d]
// tf32 mma.sync.m16n8k8. Block tile 128x128, 8 warps, warp tile 32x64.
// ===========================================================================
#define PADK 36

__global__ __launch_bounds__(256) void gemm_xw_tc(const float* __restrict__ X,
                                                  const float* __restrict__ W,
                                                  const float* __restrict__ Bb) {
    __shared__ float As[128][PADK];
    __shared__ float Bs[128][PADK];
    __shared__ float biass[128];

    const int tid  = threadIdx.x;
    const int wid  = tid >> 5, lane = tid & 31;
    const int d    = blockIdx.z;
    const int col0 = blockIdx.x * 128;
    const int row0 = blockIdx.y * 128;
    const float* Am = X + (size_t)row0 * ID;
    const float* Bm = W + ((size_t)d * NG + col0) * ID;
    float* C = g_Xg + (size_t)d * SLEN * BSZ * NG;

    // Reset the phase-2 grid barrier (gemm runs strictly before lstm_rec).
    if (blockIdx.x == 0 && blockIdx.y == 0 && blockIdx.z == 0 && tid == 0)
        g_bar = 0u;

    if (tid < 128) {
        biass[tid] = Bb[(size_t)d * 4096 + col0 + tid]
                   + Bb[(size_t)d * 4096 + 2048 + col0 + tid];
    }

    const int wm  = (wid & 3) * 32;
    const int wn  = (wid >> 2) * 64;
    const int grp = lane >> 2;
    const int thr = lane & 3;

    const int lrow = tid >> 3;
    const int lkp  = (tid & 7) * 4;

    float cr[2][8][4];
#pragma unroll
    for (int mt = 0; mt < 2; mt++)
#pragma unroll
        for (int nt = 0; nt < 8; nt++)
#pragma unroll
            for (int q = 0; q < 4; q++) cr[mt][nt][q] = 0.f;

    float4 ra[4], rb[4];
#pragma unroll
    for (int i = 0; i < 4; i++) {
        int r = lrow + i * 32;
        ra[i] = *(const float4*)(Am + (size_t)r * ID + lkp);
        rb[i] = *(const float4*)(Bm + (size_t)r * ID + lkp);
    }

#pragma unroll 1
    for (int c = 0; c < 16; c++) {
        __syncthreads();
#pragma unroll
        for (int i = 0; i < 4; i++) {
            int r = lrow + i * 32;
            float4 ca, cb;
            ca.x = __uint_as_float(f2tf32(ra[i].x));
            ca.y = __uint_as_float(f2tf32(ra[i].y));
            ca.z = __uint_as_float(f2tf32(ra[i].z));
            ca.w = __uint_as_float(f2tf32(ra[i].w));
            cb.x = __uint_as_float(f2tf32(rb[i].x));
            cb.y = __uint_as_float(f2tf32(rb[i].y));
            cb.z = __uint_as_float(f2tf32(rb[i].z));
            cb.w = __uint_as_float(f2tf32(rb[i].w));
            *(float4*)&As[r][lkp] = ca;
            *(float4*)&Bs[r][lkp] = cb;
        }
        __syncthreads();

        if (c < 15) {
            const int kk = (c + 1) * 32;
#pragma unroll
            for (int i = 0; i < 4; i++) {
                int r = lrow + i * 32;
                ra[i] = *(const float4*)(Am + (size_t)r * ID + kk + lkp);
                rb[i] = *(const float4*)(Bm + (size_t)r * ID + kk + lkp);
            }
        }

#pragma unroll
        for (int ks = 0; ks < 4; ks++) {
            const int k0 = ks * 8;
            uint32_t af[2][4];
#pragma unroll
            for (int mt = 0; mt < 2; mt++) {
                const int mr = wm + mt * 16;
                af[mt][0] = __float_as_uint(As[mr + grp][k0 + thr]);
                af[mt][1] = __float_as_uint(As[mr + grp + 8][k0 + thr]);
                af[mt][2] = __float_as_uint(As[mr + grp][k0 + thr + 4]);
                af[mt][3] = __float_as_uint(As[mr + grp + 8][k0 + thr + 4]);
            }
#pragma unroll
            for (int nt = 0; nt < 8; nt++) {
                const int nr = wn + nt * 8;
                uint32_t b0 = __float_as_uint(Bs[nr + grp][k0 + thr]);
                uint32_t b1 = __float_as_uint(Bs[nr + grp][k0 + thr + 4]);
#pragma unroll
                for (int mt = 0; mt < 2; mt++) {
                    asm volatile(
                        "mma.sync.aligned.m16n8k8.row.col.f32.tf32.tf32.f32 "
                        "{%0,%1,%2,%3}, {%4,%5,%6,%7}, {%8,%9}, {%0,%1,%2,%3};"
                        : "+f"(cr[mt][nt][0]), "+f"(cr[mt][nt][1]),
                          "+f"(cr[mt][nt][2]), "+f"(cr[mt][nt][3])
                        : "r"(af[mt][0]), "r"(af[mt][1]), "r"(af[mt][2]), "r"(af[mt][3]),
                          "r"(b0), "r"(b1));
                }
            }
        }
    }

#pragma unroll
    for (int mt = 0; mt < 2; mt++) {
        const int m0 = row0 + wm + mt * 16 + grp;
#pragma unroll
        for (int nt = 0; nt < 8; nt++) {
            const int cl = wn + nt * 8 + 2 * thr;
            float2 v0 = make_float2(cr[mt][nt][0] + biass[cl],
                                    cr[mt][nt][1] + biass[cl + 1]);
            float2 v1 = make_float2(cr[mt][nt][2] + biass[cl],
                                    cr[mt][nt][3] + biass[cl + 1]);
            *(float2*)(C + (size_t)m0 * NG + col0 + cl)       = v0;
            *(float2*)(C + (size_t)(m0 + 8) * NG + col0 + cl) = v1;
        }
    }
}

// ===========================================================================
// Phase 2: persistent bidirectional recurrence, tf32 mma.sync.
// Block = (d, 8 h-idx). Warp tiling 2m x 2n x 2k:
//   warp = (mg, ng, kg): m = mg*32..+32 (batch), gates {2ng, 2ng+1}, k half kg.
// R fragments register-resident (128 regs); h staged tf32 in smem (read 2x).
// ===========================================================================
__device__ __forceinline__ void grid_barrier(unsigned target) {
    __syncthreads();
    if (threadIdx.x == 0) {
        __threadfence();
        atomicAdd(&g_bar, 1u);
        unsigned v;
        do {
            asm volatile("ld.acquire.gpu.u32 %0, [%1];" : "=r"(v) : "l"(&g_bar) : "memory");
        } while (v < target);
    }
    __syncthreads();
}

__device__ __forceinline__ float sigmoidf_(float x) {
    return 1.f / (1.f + __expf(-x));
}

#define HS_STRIDE 72
#define HS_BYTES  (512 * HS_STRIDE * 4)

__global__ __launch_bounds__(256, 1) void lstm_rec(const float* __restrict__ R,
                                                   const int*   __restrict__ seq,
                                                   const float* __restrict__ h0,
                                                   const float* __restrict__ c0,
                                                   const float* __restrict__ P,
                                                   float* __restrict__ out) {
    extern __shared__ float hs[];            // [512][HS_STRIDE] tf32 h
    __shared__ float accs[2][4][8][65];      // [kg][gate][hl][b]
    __shared__ float xgs[4][64][9];          // [gate][b][hl]
    __shared__ float cs[8][64], c0s[8][64], h0s[8][64];
    __shared__ float Ps[3][8];
    __shared__ int   slen[BSZ];

    const int blk = blockIdx.x;
    const int d   = blk >> 6;
    const int hb  = (blk & 63) * 8;
    const int tid = threadIdx.x;
    const int wid = tid >> 5, lane = tid & 31;
    const int grp = lane >> 2, thr = lane & 3;
    const int mg  = wid & 1;                 // batch half
    const int ng  = (wid >> 1) & 1;          // gate pair {2ng, 2ng+1}
    const int kg  = wid >> 2;                // k half
    const int m0  = mg * 32;
    const int kb0 = kg * 256;

    // Preload R fragments (tf32) — constant across all steps. 2 gates x k-half.
    uint32_t Rb[2][64];
#pragma unroll
    for (int nt2 = 0; nt2 < 2; nt2++) {
        const float* Rrow = R + ((size_t)d * NG + (2 * ng + nt2) * 512 + hb + grp) * HID + kb0;
#pragma unroll
        for (int ks = 0; ks < 32; ks++) {
            Rb[nt2][2 * ks]     = f2tf32(Rrow[ks * 8 + thr]);
            Rb[nt2][2 * ks + 1] = f2tf32(Rrow[ks * 8 + thr + 4]);
        }
    }

    if (tid < BSZ) slen[tid] = seq[tid];
    if (tid < 24) {
        int w = tid / 8, hl = tid % 8;
        Ps[w][hl] = P[(size_t)d * 1536 + w * 512 + hb + hl];
    }
    for (int p = tid; p < 512; p += 256) {
        int hl = p >> 6, b = p & 63;
        size_t idx = ((size_t)d * BSZ + b) * HID + hb + hl;
        float hv = h0[idx], cv = c0[idx];
        h0s[hl][b] = hv; c0s[hl][b] = cv; cs[hl][b] = cv;
        g_h[0][d][hb + hl][b] = hv;
    }

    unsigned target = NBLK;
    grid_barrier(target); target += NBLK;    // initial h visible everywhere

    float* Yh = out + 33554432;
    float* Yc = Yh + 65536;

    const int xm = tid >> 2, xg4 = tid & 3;  // Xg stage mapping

    for (int s = 0; s < SLEN; ++s) {
        const int t   = d ? (SLEN - 1 - s) : s;
        const int cur = s & 1, nxt = cur ^ 1;

        // Prefetch this block's Xg tile (before barrier: hides latency)
        const float* xp = g_Xg + (((size_t)d * SLEN + t) * BSZ + xm) * NG + xg4 * 512 + hb;
        float4 xv0 = *(const float4*)xp;
        float4 xv1 = *(const float4*)(xp + 4);

        grid_barrier(target); target += NBLK;   // h(t) ready

        // Stage Xg into smem (conflict-free: stride 9)
        xgs[xg4][xm][0] = xv0.x; xgs[xg4][xm][1] = xv0.y;
        xgs[xg4][xm][2] = xv0.z; xgs[xg4][xm][3] = xv0.w;
        xgs[xg4][xm][4] = xv1.x; xgs[xg4][xm][5] = xv1.y;
        xgs[xg4][xm][6] = xv1.z; xgs[xg4][xm][7] = xv1.w;

        // Stage h(t) (512 x 64, tf32-converted). unroll 4: bounded reg pressure.
#pragma unroll 4
        for (int i = 0; i < 32; i++) {
            int idx = tid + i * 256;
            int k = idx >> 4, b4 = (idx & 15) * 4;
            float4 v = *(const float4*)&g_h[cur][d][k][b4];
            float4 cv;
            cv.x = __uint_as_float(f2tf32(v.x));
            cv.y = __uint_as_float(f2tf32(v.y));
            cv.z = __uint_as_float(f2tf32(v.z));
            cv.w = __uint_as_float(f2tf32(v.w));
            *(float4*)&hs[k * HS_STRIDE + b4] = cv;
        }
        __syncthreads();

        // MMA: partial G over this warp's k half.
        float acc[2][2][4];                  // [mtf][nt2][4]
#pragma unroll
        for (int mtf = 0; mtf < 2; mtf++)
#pragma unroll
            for (int nt2 = 0; nt2 < 2; nt2++)
#pragma unroll
                for (int q = 0; q < 4; q++) acc[mtf][nt2][q] = 0.f;

#pragma unroll
        for (int ks = 0; ks < 32; ks++) {
            const int r0 = (kb0 + ks * 8 + thr) * HS_STRIDE;
            const int r4 = r0 + 4 * HS_STRIDE;
            uint32_t b00 = Rb[0][2 * ks], b01 = Rb[0][2 * ks + 1];
            uint32_t b10 = Rb[1][2 * ks], b11 = Rb[1][2 * ks + 1];
#pragma unroll
            for (int mtf = 0; mtf < 2; mtf++) {
                const int mc = m0 + mtf * 16 + grp;
                uint32_t a0 = __float_as_uint(hs[r0 + mc]);
                uint32_t a1 = __float_as_uint(hs[r0 + mc + 8]);
                uint32_t a2 = __float_as_uint(hs[r4 + mc]);
                uint32_t a3 = __float_as_uint(hs[r4 + mc + 8]);
                asm volatile(
                    "mma.sync.aligned.m16n8k8.row.col.f32.tf32.tf32.f32 "
                    "{%0,%1,%2,%3}, {%4,%5,%6,%7}, {%8,%9}, {%0,%1,%2,%3};"
                    : "+f"(acc[mtf][0][0]), "+f"(acc[mtf][0][1]),
                      "+f"(acc[mtf][0][2]), "+f"(acc[mtf][0][3])
                    : "r"(a0), "r"(a1), "r"(a2), "r"(a3), "r"(b00), "r"(b01));
                asm volatile(
                    "mma.sync.aligned.m16n8k8.row.col.f32.tf32.tf32.f32 "
                    "{%0,%1,%2,%3}, {%4,%5,%6,%7}, {%8,%9}, {%0,%1,%2,%3};"
                    : "+f"(acc[mtf][1][0]), "+f"(acc[mtf][1][1]),
                      "+f"(acc[mtf][1][2]), "+f"(acc[mtf][1][3])
                    : "r"(a0), "r"(a1), "r"(a2), "r"(a3), "r"(b10), "r"(b11));
            }
        }

        // Exchange: fragments -> accs[kg][gate][hl][b]
#pragma unroll
        for (int mtf = 0; mtf < 2; mtf++) {
            const int m = m0 + mtf * 16 + grp;
#pragma unroll
            for (int nt2 = 0; nt2 < 2; nt2++) {
                const int g = 2 * ng + nt2;
                accs[kg][g][2 * thr]    [m]     = acc[mtf][nt2][0];
                accs[kg][g][2 * thr + 1][m]     = acc[mtf][nt2][1];
                accs[kg][g][2 * thr]    [m + 8] = acc[mtf][nt2][2];
                accs[kg][g][2 * thr + 1][m + 8] = acc[mtf][nt2][3];
            }
        }
        __syncthreads();

        // Elementwise LSTM cell + peephole + mask
        for (int p = tid; p < 512; p += 256) {
            int hl = p >> 6, b = p & 63;
            float gi = accs[0][0][hl][b] + accs[1][0][hl][b] + xgs[0][b][hl];
            float go = accs[0][1][hl][b] + accs[1][1][hl][b] + xgs[1][b][hl];
            float gf = accs[0][2][hl][b] + accs[1][2][hl][b] + xgs[2][b][hl];
            float gg = accs[0][3][hl][b] + accs[1][3][hl][b] + xgs[3][b][hl];
            float c  = cs[hl][b];
            float iv = sigmoidf_(gi + Ps[0][hl] * c);
            float fv = sigmoidf_(gf + Ps[1][hl] * c);
            float ct = tanhf(gg);
            float cn = fv * c + iv * ct;
            float ov = sigmoidf_(go + Ps[2][hl] * cn);
            float hn = ov * tanhf(cn);
            if (t >= slen[b]) { hn = h0s[hl][b]; cn = c0s[hl][b]; }
            cs[hl][b] = cn;
            g_h[nxt][d][hb + hl][b] = hn;
            out[(((size_t)t * 2 + d) * BSZ + b) * HID + hb + hl] = hn;
            if (s == SLEN - 1) {
                size_t fi = ((size_t)d * BSZ + b) * HID + hb + hl;
                Yh[fi] = hn;
                Yc[fi] = cn;
            }
        }
    }
}

// ---------------------------------------------------------------------------
extern "C" void kernel_launch(void* const* d_in, const int* in_sizes, int n_in,
                              void* d_out, int out_size) {
    const float* X   = (const float*)d_in[0];
    const float* W   = (const float*)d_in[1];
    const float* R   = (const float*)d_in[2];
    const float* Bb  = (const float*)d_in[3];
    const int*   sl  = (const int*)  d_in[4];
    const float* h0  = (const float*)d_in[5];
    const float* c0  = (const float*)d_in[6];
    const float* P   = (const float*)d_in[7];
    float* out = (float*)d_out;

    static int configured = 0;
    if (!configured) {
        cudaFuncSetAttribute(lstm_rec, cudaFuncAttributeMaxDynamicSharedMemorySize,
                             HS_BYTES);
        configured = 1;
    }

    gemm_xw_tc<<<dim3(16, 256, 2), 256>>>(X, W, Bb);
    lstm_rec<<<NBLK, 256, HS_BYTES>>>(R, sl, h0, c0, P, out);
}

// round 6
// speedup vs baseline: 3.8904x; 1.3970x over previous
#include <cuda_runtime.h>
#include <cuda_fp16.h>
#include <cstdint>

// Problem constants
#define SLEN 512
#define BSZ  64
#define ID   512
#define HID  512
#define NG   2048   // 4*H
#define NBLK 128    // persistent blocks for phase 2

// Scratch (device globals: allocation-free)
static __device__ float    g_Xg[134217728];        // (D, S, B, 4H)
static __device__ __half   g_h[2][2][HID][BSZ];    // [buf][d][h][b], fp16
static __device__ unsigned g_bar;

__device__ __forceinline__ uint32_t f2tf32(float x) {
    uint32_t r;
    asm("cvt.rna.tf32.f32 %0, %1;" : "=r"(r) : "f"(x));
    return r;
}
__device__ __forceinline__ uint32_t smem_u32(const void* p) {
    uint32_t a;
    asm("{ .reg .u64 t; cvta.to.shared.u64 t, %1; cvt.u32.u64 %0, t; }"
        : "=r"(a) : "l"(p));
    return a;
}

// ===========================================================================
// Phase 1: Xg[d, r, :] = X[r,:] @ W[d]^T + Wb[d] + Rb[d]
// tf32 mma.sync.m16n8k8. Block tile 128x128, 8 warps, warp tile 32x64.
// (unchanged from R5 — proven)
// ===========================================================================
#define PADK 36

__global__ __launch_bounds__(256) void gemm_xw_tc(const float* __restrict__ X,
                                                  const float* __restrict__ W,
                                                  const float* __restrict__ Bb) {
    __shared__ float As[128][PADK];
    __shared__ float Bs[128][PADK];
    __shared__ float biass[128];

    const int tid  = threadIdx.x;
    const int wid  = tid >> 5, lane = tid & 31;
    const int d    = blockIdx.z;
    const int col0 = blockIdx.x * 128;
    const int row0 = blockIdx.y * 128;
    const float* Am = X + (size_t)row0 * ID;
    const float* Bm = W + ((size_t)d * NG + col0) * ID;
    float* C = g_Xg + (size_t)d * SLEN * BSZ * NG;

    if (blockIdx.x == 0 && blockIdx.y == 0 && blockIdx.z == 0 && tid == 0)
        g_bar = 0u;

    if (tid < 128) {
        biass[tid] = Bb[(size_t)d * 4096 + col0 + tid]
                   + Bb[(size_t)d * 4096 + 2048 + col0 + tid];
    }

    const int wm  = (wid & 3) * 32;
    const int wn  = (wid >> 2) * 64;
    const int grp = lane >> 2;
    const int thr = lane & 3;

    const int lrow = tid >> 3;
    const int lkp  = (tid & 7) * 4;

    float cr[2][8][4];
#pragma unroll
    for (int mt = 0; mt < 2; mt++)
#pragma unroll
        for (int nt = 0; nt < 8; nt++)
#pragma unroll
            for (int q = 0; q < 4; q++) cr[mt][nt][q] = 0.f;

    float4 ra[4], rb[4];
#pragma unroll
    for (int i = 0; i < 4; i++) {
        int r = lrow + i * 32;
        ra[i] = *(const float4*)(Am + (size_t)r * ID + lkp);
        rb[i] = *(const float4*)(Bm + (size_t)r * ID + lkp);
    }

#pragma unroll 1
    for (int c = 0; c < 16; c++) {
        __syncthreads();
#pragma unroll
        for (int i = 0; i < 4; i++) {
            int r = lrow + i * 32;
            float4 ca, cb;
            ca.x = __uint_as_float(f2tf32(ra[i].x));
            ca.y = __uint_as_float(f2tf32(ra[i].y));
            ca.z = __uint_as_float(f2tf32(ra[i].z));
            ca.w = __uint_as_float(f2tf32(ra[i].w));
            cb.x = __uint_as_float(f2tf32(rb[i].x));
            cb.y = __uint_as_float(f2tf32(rb[i].y));
            cb.z = __uint_as_float(f2tf32(rb[i].z));
            cb.w = __uint_as_float(f2tf32(rb[i].w));
            *(float4*)&As[r][lkp] = ca;
            *(float4*)&Bs[r][lkp] = cb;
        }
        __syncthreads();

        if (c < 15) {
            const int kk = (c + 1) * 32;
#pragma unroll
            for (int i = 0; i < 4; i++) {
                int r = lrow + i * 32;
                ra[i] = *(const float4*)(Am + (size_t)r * ID + kk + lkp);
                rb[i] = *(const float4*)(Bm + (size_t)r * ID + kk + lkp);
            }
        }

#pragma unroll
        for (int ks = 0; ks < 4; ks++) {
            const int k0 = ks * 8;
            uint32_t af[2][4];
#pragma unroll
            for (int mt = 0; mt < 2; mt++) {
                const int mr = wm + mt * 16;
                af[mt][0] = __float_as_uint(As[mr + grp][k0 + thr]);
                af[mt][1] = __float_as_uint(As[mr + grp + 8][k0 + thr]);
                af[mt][2] = __float_as_uint(As[mr + grp][k0 + thr + 4]);
                af[mt][3] = __float_as_uint(As[mr + grp + 8][k0 + thr + 4]);
            }
#pragma unroll
            for (int nt = 0; nt < 8; nt++) {
                const int nr = wn + nt * 8;
                uint32_t b0 = __float_as_uint(Bs[nr + grp][k0 + thr]);
                uint32_t b1 = __float_as_uint(Bs[nr + grp][k0 + thr + 4]);
#pragma unroll
                for (int mt = 0; mt < 2; mt++) {
                    asm volatile(
                        "mma.sync.aligned.m16n8k8.row.col.f32.tf32.tf32.f32 "
                        "{%0,%1,%2,%3}, {%4,%5,%6,%7}, {%8,%9}, {%0,%1,%2,%3};"
                        : "+f"(cr[mt][nt][0]), "+f"(cr[mt][nt][1]),
                          "+f"(cr[mt][nt][2]), "+f"(cr[mt][nt][3])
                        : "r"(af[mt][0]), "r"(af[mt][1]), "r"(af[mt][2]), "r"(af[mt][3]),
                          "r"(b0), "r"(b1));
                }
            }
        }
    }

#pragma unroll
    for (int mt = 0; mt < 2; mt++) {
        const int m0 = row0 + wm + mt * 16 + grp;
#pragma unroll
        for (int nt = 0; nt < 8; nt++) {
            const int cl = wn + nt * 8 + 2 * thr;
            float2 v0 = make_float2(cr[mt][nt][0] + biass[cl],
                                    cr[mt][nt][1] + biass[cl + 1]);
            float2 v1 = make_float2(cr[mt][nt][2] + biass[cl],
                                    cr[mt][nt][3] + biass[cl + 1]);
            *(float2*)(C + (size_t)m0 * NG + col0 + cl)       = v0;
            *(float2*)(C + (size_t)(m0 + 8) * NG + col0 + cl) = v1;
        }
    }
}

// ===========================================================================
// Phase 2: persistent bidirectional recurrence, fp16 mma.m16n8k16.
// 512 threads, 16 warps = 2mg x 2ng x 4kg. h fp16 in gmem, cp.async staged,
// ldmatrix.x4.trans fragments. R fragments register-resident (fp16).
// ===========================================================================
__device__ __forceinline__ void grid_barrier(unsigned target) {
    __syncthreads();
    if (threadIdx.x == 0) {
        __threadfence();
        atomicAdd(&g_bar, 1u);
        unsigned v;
        do {
            asm volatile("ld.acquire.gpu.u32 %0, [%1];" : "=r"(v) : "l"(&g_bar) : "memory");
        } while (v < target);
    }
    __syncthreads();
}

__device__ __forceinline__ float sigmoidf_(float x) {
    return 1.f / (1.f + __expf(-x));
}

#define HS_STRIDE 72                          // halves; 144B rows: 16B-aligned, conflict-free
#define HS_BYTES  (512 * HS_STRIDE * 2)

__global__ __launch_bounds__(512, 1) void lstm_rec(const float* __restrict__ R,
                                                   const int*   __restrict__ seq,
                                                   const float* __restrict__ h0,
                                                   const float* __restrict__ c0,
                                                   const float* __restrict__ P,
                                                   float* __restrict__ out) {
    extern __shared__ __half hs[];           // [512][HS_STRIDE] fp16 h
    __shared__ float accs[4][4][8][65];      // [kg][gate][hl][b]
    __shared__ float xgs[4][64][9];          // [gate][b][hl]
    __shared__ float cs[8][64], c0s[8][64], h0s[8][64];
    __shared__ float Ps[3][8];
    __shared__ int   slen[BSZ];

    const int blk = blockIdx.x;
    const int d   = blk >> 6;
    const int hb  = (blk & 63) * 8;
    const int tid = threadIdx.x;
    const int wid = tid >> 5, lane = tid & 31;
    const int grp = lane >> 2, thr = lane & 3;
    const int mg  = wid & 1;                 // batch half
    const int ng  = (wid >> 1) & 1;          // gate pair {2ng, 2ng+1}
    const int kg  = wid >> 2;                // k quarter (0..3)
    const int m0  = mg * 32;
    const int kb0 = kg * 128;

    const uint32_t hs_b = smem_u32(hs);

    // Lane-constant ldmatrix address components (x4.trans):
    // seg 0: m+0,k+0  seg1: m+8,k+0  seg2: m+0,k+8  seg3: m+8,k+8; row = lane&7.
    const int seg   = lane >> 3;
    const int laneK = ((seg >> 1) << 3) + (lane & 7);
    const int laneM = (seg & 1) << 3;

    // Preload R fragments (fp16 half2) — constant across steps.
    // B frag: n = grp, k = {2thr,2thr+1} (lo) / +8 (hi).
    uint32_t Rlo[2][8], Rhi[2][8];
#pragma unroll
    for (int nt2 = 0; nt2 < 2; nt2++) {
        const float* Rrow = R + ((size_t)d * NG + (2 * ng + nt2) * 512 + hb + grp) * HID + kb0;
#pragma unroll
        for (int ks = 0; ks < 8; ks++) {
            const int k = ks * 16;
            __half2 lo = __floats2half2_rn(Rrow[k + 2 * thr], Rrow[k + 2 * thr + 1]);
            __half2 hi = __floats2half2_rn(Rrow[k + 2 * thr + 8], Rrow[k + 2 * thr + 9]);
            Rlo[nt2][ks] = *(uint32_t*)&lo;
            Rhi[nt2][ks] = *(uint32_t*)&hi;
        }
    }

    if (tid < BSZ) slen[tid] = seq[tid];
    if (tid < 24) {
        int w = tid / 8, hl = tid % 8;
        Ps[w][hl] = P[(size_t)d * 1536 + w * 512 + hb + hl];
    }
    if (tid < 512) {
        int hl = tid >> 6, b = tid & 63;
        size_t idx = ((size_t)d * BSZ + b) * HID + hb + hl;
        float hv = h0[idx], cv = c0[idx];
        h0s[hl][b] = hv; c0s[hl][b] = cv; cs[hl][b] = cv;
        g_h[0][d][hb + hl][b] = __float2half(hv);
    }

    unsigned target = NBLK;
    grid_barrier(target); target += NBLK;    // initial h visible everywhere

    float* Yh = out + 33554432;
    float* Yc = Yh + 65536;

    const int xb = tid >> 3, xq = tid & 7;   // Xg stage: gate = xq>>1, half4 = xq&1
    const int xgate = xq >> 1, xh4 = (xq & 1) * 4;

    for (int s = 0; s < SLEN; ++s) {
        const int t   = d ? (SLEN - 1 - s) : s;
        const int cur = s & 1, nxt = cur ^ 1;

        // Prefetch this block's Xg tile before the barrier
        const float* xp = g_Xg + (((size_t)d * SLEN + t) * BSZ + xb) * NG
                        + xgate * 512 + hb + xh4;
        float4 xv = *(const float4*)xp;

        grid_barrier(target); target += NBLK;   // h(t) ready

        xgs[xgate][xb][xh4 + 0] = xv.x;
        xgs[xgate][xb][xh4 + 1] = xv.y;
        xgs[xgate][xb][xh4 + 2] = xv.z;
        xgs[xgate][xb][xh4 + 3] = xv.w;

        // Stage h(t): 512x64 halves = 64KB, pure 16B async copies.
#pragma unroll
        for (int i = 0; i < 8; i++) {
            int c = tid + i * 512;
            int k = c >> 3, b8 = (c & 7) * 8;
            uint32_t dst = hs_b + (uint32_t)(k * HS_STRIDE + b8) * 2;
            const __half* src = &g_h[cur][d][k][b8];
            asm volatile("cp.async.cg.shared.global [%0], [%1], 16;"
                         :: "r"(dst), "l"(src));
        }
        asm volatile("cp.async.commit_group;");
        asm volatile("cp.async.wait_group 0;");
        __syncthreads();

        // MMA: partial G over this warp's k quarter (k=128, 8 k16 steps).
        float acc[2][2][4];
#pragma unroll
        for (int mtf = 0; mtf < 2; mtf++)
#pragma unroll
            for (int nt2 = 0; nt2 < 2; nt2++)
#pragma unroll
                for (int q = 0; q < 4; q++) acc[mtf][nt2][q] = 0.f;

#pragma unroll
        for (int ks = 0; ks < 8; ks++) {
            const int kb = kb0 + ks * 16 + laneK;
#pragma unroll
            for (int mtf = 0; mtf < 2; mtf++) {
                const int mb = m0 + mtf * 16 + laneM;
                uint32_t addr = hs_b + (uint32_t)(kb * HS_STRIDE + mb) * 2;
                uint32_t a0, a1, a2, a3;
                asm volatile(
                    "ldmatrix.sync.aligned.m8n8.x4.trans.shared.b16 {%0,%1,%2,%3}, [%4];"
                    : "=r"(a0), "=r"(a1), "=r"(a2), "=r"(a3) : "r"(addr));
#pragma unroll
                for (int nt2 = 0; nt2 < 2; nt2++) {
                    asm volatile(
                        "mma.sync.aligned.m16n8k16.row.col.f32.f16.f16.f32 "
                        "{%0,%1,%2,%3}, {%4,%5,%6,%7}, {%8,%9}, {%0,%1,%2,%3};"
                        : "+f"(acc[mtf][nt2][0]), "+f"(acc[mtf][nt2][1]),
                          "+f"(acc[mtf][nt2][2]), "+f"(acc[mtf][nt2][3])
                        : "r"(a0), "r"(a1), "r"(a2), "r"(a3),
                          "r"(Rlo[nt2][ks]), "r"(Rhi[nt2][ks]));
                }
            }
        }

        // Exchange: D frag (row=batch=grp, col=hl=2thr) -> accs[kg][gate][hl][b]
#pragma unroll
        for (int mtf = 0; mtf < 2; mtf++) {
            const int m = m0 + mtf * 16 + grp;
#pragma unroll
            for (int nt2 = 0; nt2 < 2; nt2++) {
                const int g = 2 * ng + nt2;
                accs[kg][g][2 * thr]    [m]     = acc[mtf][nt2][0];
                accs[kg][g][2 * thr + 1][m]     = acc[mtf][nt2][1];
                accs[kg][g][2 * thr]    [m + 8] = acc[mtf][nt2][2];
                accs[kg][g][2 * thr + 1][m + 8] = acc[mtf][nt2][3];
            }
        }
        __syncthreads();

        // Elementwise LSTM cell + peephole + mask (512 threads, 1 elem each)
        {
            int hl = tid >> 6, b = tid & 63;
            float gi = accs[0][0][hl][b] + accs[1][0][hl][b]
                     + accs[2][0][hl][b] + accs[3][0][hl][b] + xgs[0][b][hl];
            float go = accs[0][1][hl][b] + accs[1][1][hl][b]
                     + accs[2][1][hl][b] + accs[3][1][hl][b] + xgs[1][b][hl];
            float gf = accs[0][2][hl][b] + accs[1][2][hl][b]
                     + accs[2][2][hl][b] + accs[3][2][hl][b] + xgs[2][b][hl];
            float gg = accs[0][3][hl][b] + accs[1][3][hl][b]
                     + accs[2][3][hl][b] + accs[3][3][hl][b] + xgs[3][b][hl];
            float c  = cs[hl][b];
            float iv = sigmoidf_(gi + Ps[0][hl] * c);
            float fv = sigmoidf_(gf + Ps[1][hl] * c);
            float ct = tanhf(gg);
            float cn = fv * c + iv * ct;
            float ov = sigmoidf_(go + Ps[2][hl] * cn);
            float hn = ov * tanhf(cn);
            if (t >= slen[b]) { hn = h0s[hl][b]; cn = c0s[hl][b]; }
            cs[hl][b] = cn;
            g_h[nxt][d][hb + hl][b] = __float2half(hn);
            out[(((size_t)t * 2 + d) * BSZ + b) * HID + hb + hl] = hn;
            if (s == SLEN - 1) {
                size_t fi = ((size_t)d * BSZ + b) * HID + hb + hl;
                Yh[fi] = hn;
                Yc[fi] = cn;
            }
        }
    }
}

// ---------------------------------------------------------------------------
extern "C" void kernel_launch(void* const* d_in, const int* in_sizes, int n_in,
                              void* d_out, int out_size) {
    const float* X   = (const float*)d_in[0];
    const float* W   = (const float*)d_in[1];
    const float* R   = (const float*)d_in[2];
    const float* Bb  = (const float*)d_in[3];
    const int*   sl  = (const int*)  d_in[4];
    const float* h0  = (const float*)d_in[5];
    const float* c0  = (const float*)d_in[6];
    const float* P   = (const float*)d_in[7];
    float* out = (float*)d_out;

    static int configured = 0;
    if (!configured) {
        cudaFuncSetAttribute(lstm_rec, cudaFuncAttributeMaxDynamicSharedMemorySize,
                             HS_BYTES);
        configured = 1;
    }

    gemm_xw_tc<<<dim3(16, 256, 2), 256>>>(X, W, Bb);
    lstm_rec<<<NBLK, 512, HS_BYTES>>>(R, sl, h0, c0, P, out);
}

// round 7
// speedup vs baseline: 4.2468x; 1.0916x over previous
#include <cuda_runtime.h>
#include <cuda_fp16.h>
#include <cstdint>

// Problem constants
#define SLEN 512
#define BSZ  64
#define ID   512
#define HID  512
#define NG   2048   // 4*H
#define NBLK 128    // total persistent blocks for phase 2
#define NBLKD 64    // per direction

// Scratch (device globals: allocation-free)
static __device__ float    g_Xg[134217728];        // (D, S, B, 4H)
static __device__ __half   g_h[2][2][HID][BSZ];    // [buf][d][h][b], fp16
static __device__ unsigned g_barD[2];

__device__ __forceinline__ uint32_t smem_u32(const void* p) {
    uint32_t a;
    asm("{ .reg .u64 t; cvta.to.shared.u64 t, %1; cvt.u32.u64 %0, t; }"
        : "=r"(a) : "l"(p));
    return a;
}

// ===========================================================================
// Phase 1: Xg[d, r, :] = X[r,:] @ W[d]^T + Wb[d] + Rb[d]
// fp16 mma.sync.m16n8k16, fp32 accum. Block tile 128x128, 8 warps (4m x 2n),
// warp tile 32x64, K-chunk 32. smem [row][k] fp16, stride 40 (conflict-free).
// ===========================================================================
#define PSTR 40

__global__ __launch_bounds__(256) void gemm_xw_fp16(const float* __restrict__ X,
                                                    const float* __restrict__ W,
                                                    const float* __restrict__ Bb) {
    __shared__ __half As[128][PSTR];
    __shared__ __half Bs[128][PSTR];
    __shared__ float biass[128];

    const int tid  = threadIdx.x;
    const int wid  = tid >> 5, lane = tid & 31;
    const int d    = blockIdx.z;
    const int col0 = blockIdx.x * 128;
    const int row0 = blockIdx.y * 128;
    const float* Am = X + (size_t)row0 * ID;
    const float* Bm = W + ((size_t)d * NG + col0) * ID;
    float* C = g_Xg + (size_t)d * SLEN * BSZ * NG;

    if (blockIdx.x == 0 && blockIdx.y == 0 && blockIdx.z == 0 && tid == 0) {
        g_barD[0] = 0u;
        g_barD[1] = 0u;
    }

    if (tid < 128) {
        biass[tid] = Bb[(size_t)d * 4096 + col0 + tid]
                   + Bb[(size_t)d * 4096 + 2048 + col0 + tid];
    }

    const int wm  = (wid & 3) * 32;
    const int wn  = (wid >> 2) * 64;
    const int grp = lane >> 2;
    const int thr = lane & 3;

    // ldmatrix x4 non-trans lane address components: rows 0-15 from lanes 0-15
    // (k lo 8), rows 0-15 from lanes 16-31 (k hi 8).
    const int aM  = lane & 15;
    const int aK8 = (lane >> 4) << 3;

    const int lrow = tid >> 3;        // 0..31
    const int lkp  = (tid & 7) * 4;   // 0,4,...,28

    float cr[2][8][4];
#pragma unroll
    for (int mt = 0; mt < 2; mt++)
#pragma unroll
        for (int nt = 0; nt < 8; nt++)
#pragma unroll
            for (int q = 0; q < 4; q++) cr[mt][nt][q] = 0.f;

    float4 ra[4], rb[4];
#pragma unroll
    for (int i = 0; i < 4; i++) {
        int r = lrow + i * 32;
        ra[i] = *(const float4*)(Am + (size_t)r * ID + lkp);
        rb[i] = *(const float4*)(Bm + (size_t)r * ID + lkp);
    }

#pragma unroll 1
    for (int c = 0; c < 16; c++) {
        __syncthreads();
#pragma unroll
        for (int i = 0; i < 4; i++) {
            int r = lrow + i * 32;
            __half2 a01 = __floats2half2_rn(ra[i].x, ra[i].y);
            __half2 a23 = __floats2half2_rn(ra[i].z, ra[i].w);
            __half2 b01 = __floats2half2_rn(rb[i].x, rb[i].y);
            __half2 b23 = __floats2half2_rn(rb[i].z, rb[i].w);
            uint2 va = make_uint2(*(uint32_t*)&a01, *(uint32_t*)&a23);
            uint2 vb = make_uint2(*(uint32_t*)&b01, *(uint32_t*)&b23);
            *(uint2*)&As[r][lkp] = va;
            *(uint2*)&Bs[r][lkp] = vb;
        }
        __syncthreads();

        if (c < 15) {
            const int kk = (c + 1) * 32;
#pragma unroll
            for (int i = 0; i < 4; i++) {
                int r = lrow + i * 32;
                ra[i] = *(const float4*)(Am + (size_t)r * ID + kk + lkp);
                rb[i] = *(const float4*)(Bm + (size_t)r * ID + kk + lkp);
            }
        }

#pragma unroll
        for (int ks = 0; ks < 2; ks++) {
            const int k0 = ks * 16;
            uint32_t af[2][4];
#pragma unroll
            for (int mt = 0; mt < 2; mt++) {
                uint32_t addr = smem_u32(&As[wm + mt * 16 + aM][k0 + aK8]);
                asm volatile(
                    "ldmatrix.sync.aligned.m8n8.x4.shared.b16 {%0,%1,%2,%3}, [%4];"
                    : "=r"(af[mt][0]), "=r"(af[mt][1]), "=r"(af[mt][2]), "=r"(af[mt][3])
                    : "r"(addr));
            }
#pragma unroll
            for (int nt16 = 0; nt16 < 4; nt16++) {
                uint32_t r0, r1, r2, r3;
                uint32_t addr = smem_u32(&Bs[wn + nt16 * 16 + aM][k0 + aK8]);
                asm volatile(
                    "ldmatrix.sync.aligned.m8n8.x4.shared.b16 {%0,%1,%2,%3}, [%4];"
                    : "=r"(r0), "=r"(r1), "=r"(r2), "=r"(r3) : "r"(addr));
#pragma unroll
                for (int mt = 0; mt < 2; mt++) {
                    asm volatile(
                        "mma.sync.aligned.m16n8k16.row.col.f32.f16.f16.f32 "
                        "{%0,%1,%2,%3}, {%4,%5,%6,%7}, {%8,%9}, {%0,%1,%2,%3};"
                        : "+f"(cr[mt][2 * nt16][0]), "+f"(cr[mt][2 * nt16][1]),
                          "+f"(cr[mt][2 * nt16][2]), "+f"(cr[mt][2 * nt16][3])
                        : "r"(af[mt][0]), "r"(af[mt][1]), "r"(af[mt][2]), "r"(af[mt][3]),
                          "r"(r0), "r"(r2));
                    asm volatile(
                        "mma.sync.aligned.m16n8k16.row.col.f32.f16.f16.f32 "
                        "{%0,%1,%2,%3}, {%4,%5,%6,%7}, {%8,%9}, {%0,%1,%2,%3};"
                        : "+f"(cr[mt][2 * nt16 + 1][0]), "+f"(cr[mt][2 * nt16 + 1][1]),
                          "+f"(cr[mt][2 * nt16 + 1][2]), "+f"(cr[mt][2 * nt16 + 1][3])
                        : "r"(af[mt][0]), "r"(af[mt][1]), "r"(af[mt][2]), "r"(af[mt][3]),
                          "r"(r1), "r"(r3));
                }
            }
        }
    }

#pragma unroll
    for (int mt = 0; mt < 2; mt++) {
        const int m0 = row0 + wm + mt * 16 + grp;
#pragma unroll
        for (int nt = 0; nt < 8; nt++) {
            const int cl = wn + nt * 8 + 2 * thr;
            float2 v0 = make_float2(cr[mt][nt][0] + biass[cl],
                                    cr[mt][nt][1] + biass[cl + 1]);
            float2 v1 = make_float2(cr[mt][nt][2] + biass[cl],
                                    cr[mt][nt][3] + biass[cl + 1]);
            *(float2*)(C + (size_t)m0 * NG + col0 + cl)       = v0;
            *(float2*)(C + (size_t)(m0 + 8) * NG + col0 + cl) = v1;
        }
    }
}

// ===========================================================================
// Phase 2: persistent bidirectional recurrence, fp16 mma.m16n8k16.
// Per-direction grid barrier (64 CTAs). k-quarter staging with named barriers.
// ===========================================================================
__device__ __forceinline__ void grid_barrier(unsigned* ctr, unsigned target) {
    __syncthreads();
    if (threadIdx.x == 0) {
        __threadfence();
        atomicAdd(ctr, 1u);
        unsigned v;
        do {
            asm volatile("ld.acquire.gpu.u32 %0, [%1];" : "=r"(v) : "l"(ctr) : "memory");
        } while (v < target);
    }
    __syncthreads();
}

__device__ __forceinline__ float sigmoidf_(float x) {
    return 1.f / (1.f + __expf(-x));
}

#define HS_STRIDE 72
#define HS_BYTES  (512 * HS_STRIDE * 2)

__global__ __launch_bounds__(512, 1) void lstm_rec(const float* __restrict__ R,
                                                   const int*   __restrict__ seq,
                                                   const float* __restrict__ h0,
                                                   const float* __restrict__ c0,
                                                   const float* __restrict__ P,
                                                   float* __restrict__ out) {
    extern __shared__ __half hs[];           // [512][HS_STRIDE] fp16 h
    __shared__ float accs[4][4][8][65];      // [kg][gate][hl][b]
    __shared__ float xgs[4][64][9];          // [gate][b][hl]
    __shared__ float cs[8][64], c0s[8][64], h0s[8][64];
    __shared__ float Ps[3][8];
    __shared__ int   slen[BSZ];

    const int blk = blockIdx.x;
    const int d   = blk >> 6;
    const int hb  = (blk & 63) * 8;
    const int tid = threadIdx.x;
    const int wid = tid >> 5, lane = tid & 31;
    const int grp = lane >> 2, thr = lane & 3;
    const int mg  = wid & 1;                 // batch half
    const int ng  = (wid >> 1) & 1;          // gate pair {2ng, 2ng+1}
    const int kg  = wid >> 2;                // k quarter (0..3)
    const int m0  = mg * 32;
    const int kb0 = kg * 128;

    unsigned* bar = &g_barD[d];

    const uint32_t hs_b = smem_u32(hs);

    // ldmatrix x4.trans lane components
    const int seg   = lane >> 3;
    const int laneK = ((seg >> 1) << 3) + (lane & 7);
    const int laneM = (seg & 1) << 3;

    // Preload R fragments (fp16) — constant across steps.
    uint32_t Rlo[2][8], Rhi[2][8];
#pragma unroll
    for (int nt2 = 0; nt2 < 2; nt2++) {
        const float* Rrow = R + ((size_t)d * NG + (2 * ng + nt2) * 512 + hb + grp) * HID + kb0;
#pragma unroll
        for (int ks = 0; ks < 8; ks++) {
            const int k = ks * 16;
            __half2 lo = __floats2half2_rn(Rrow[k + 2 * thr], Rrow[k + 2 * thr + 1]);
            __half2 hi = __floats2half2_rn(Rrow[k + 2 * thr + 8], Rrow[k + 2 * thr + 9]);
            Rlo[nt2][ks] = *(uint32_t*)&lo;
            Rhi[nt2][ks] = *(uint32_t*)&hi;
        }
    }

    if (tid < BSZ) slen[tid] = seq[tid];
    if (tid < 24) {
        int w = tid / 8, hl = tid % 8;
        Ps[w][hl] = P[(size_t)d * 1536 + w * 512 + hb + hl];
    }
    {
        int hl = tid >> 6, b = tid & 63;
        size_t idx = ((size_t)d * BSZ + b) * HID + hb + hl;
        float hv = h0[idx], cv = c0[idx];
        h0s[hl][b] = hv; c0s[hl][b] = cv; cs[hl][b] = cv;
        g_h[0][d][hb + hl][b] = __float2half(hv);
    }

    unsigned target = NBLKD;
    grid_barrier(bar, target); target += NBLKD;   // initial h visible (per dir)

    float* Yh = out + 33554432;
    float* Yc = Yh + 65536;

    const int xb = tid >> 3, xq = tid & 7;
    const int xgate = xq >> 1, xh4 = (xq & 1) * 4;

    const int sgrp   = tid >> 7;              // staging group == warp's kg
    const int slocal = tid & 127;
    const int skb0   = sgrp * 128;

    for (int s = 0; s < SLEN; ++s) {
        const int t   = d ? (SLEN - 1 - s) : s;
        const int cur = s & 1, nxt = cur ^ 1;

        // Prefetch this block's Xg tile before the barrier
        const float* xp = g_Xg + (((size_t)d * SLEN + t) * BSZ + xb) * NG
                        + xgate * 512 + hb + xh4;
        float4 xv = *(const float4*)xp;

        grid_barrier(bar, target); target += NBLKD;   // h(t) ready (this dir)

        xgs[xgate][xb][xh4 + 0] = xv.x;
        xgs[xgate][xb][xh4 + 1] = xv.y;
        xgs[xgate][xb][xh4 + 2] = xv.z;
        xgs[xgate][xb][xh4 + 3] = xv.w;

        // Stage own k-quarter only: 16KB per 128-thread group, then group bar.
#pragma unroll
        for (int i = 0; i < 8; i++) {
            int c = slocal + i * 128;
            int k = skb0 + (c >> 3), b8 = (c & 7) * 8;
            uint32_t dst = hs_b + (uint32_t)(k * HS_STRIDE + b8) * 2;
            const __half* src = &g_h[cur][d][k][b8];
            asm volatile("cp.async.cg.shared.global [%0], [%1], 16;"
                         :: "r"(dst), "l"(src));
        }
        asm volatile("cp.async.commit_group;");
        asm volatile("cp.async.wait_group 0;");
        asm volatile("bar.sync %0, 128;" :: "r"(1 + sgrp) : "memory");

        // MMA: partial G over this warp's k quarter (8 k16 steps).
        float acc[2][2][4];
#pragma unroll
        for (int mtf = 0; mtf < 2; mtf++)
#pragma unroll
            for (int nt2 = 0; nt2 < 2; nt2++)
#pragma unroll
                for (int q = 0; q < 4; q++) acc[mtf][nt2][q] = 0.f;

#pragma unroll
        for (int ks = 0; ks < 8; ks++) {
            const int kb = kb0 + ks * 16 + laneK;
#pragma unroll
            for (int mtf = 0; mtf < 2; mtf++) {
                const int mb = m0 + mtf * 16 + laneM;
                uint32_t addr = hs_b + (uint32_t)(kb * HS_STRIDE + mb) * 2;
                uint32_t a0, a1, a2, a3;
                asm volatile(
                    "ldmatrix.sync.aligned.m8n8.x4.trans.shared.b16 {%0,%1,%2,%3}, [%4];"
                    : "=r"(a0), "=r"(a1), "=r"(a2), "=r"(a3) : "r"(addr));
#pragma unroll
                for (int nt2 = 0; nt2 < 2; nt2++) {
                    asm volatile(
                        "mma.sync.aligned.m16n8k16.row.col.f32.f16.f16.f32 "
                        "{%0,%1,%2,%3}, {%4,%5,%6,%7}, {%8,%9}, {%0,%1,%2,%3};"
                        : "+f"(acc[mtf][nt2][0]), "+f"(acc[mtf][nt2][1]),
                          "+f"(acc[mtf][nt2][2]), "+f"(acc[mtf][nt2][3])
                        : "r"(a0), "r"(a1), "r"(a2), "r"(a3),
                          "r"(Rlo[nt2][ks]), "r"(Rhi[nt2][ks]));
                }
            }
        }

        // Exchange: fragments -> accs[kg][gate][hl][b]
#pragma unroll
        for (int mtf = 0; mtf < 2; mtf++) {
            const int m = m0 + mtf * 16 + grp;
#pragma unroll
            for (int nt2 = 0; nt2 < 2; nt2++) {
                const int g = 2 * ng + nt2;
                accs[kg][g][2 * thr]    [m]     = acc[mtf][nt2][0];
                accs[kg][g][2 * thr + 1][m]     = acc[mtf][nt2][1];
                accs[kg][g][2 * thr]    [m + 8] = acc[mtf][nt2][2];
                accs[kg][g][2 * thr + 1][m + 8] = acc[mtf][nt2][3];
            }
        }
        __syncthreads();

        // Elementwise LSTM cell + peephole + mask (512 threads, 1 elem each)
        {
            int hl = tid >> 6, b = tid & 63;
            float gi = accs[0][0][hl][b] + accs[1][0][hl][b]
                     + accs[2][0][hl][b] + accs[3][0][hl][b] + xgs[0][b][hl];
            float go = accs[0][1][hl][b] + accs[1][1][hl][b]
                     + accs[2][1][hl][b] + accs[3][1][hl][b] + xgs[1][b][hl];
            float gf = accs[0][2][hl][b] + accs[1][2][hl][b]
                     + accs[2][2][hl][b] + accs[3][2][hl][b] + xgs[2][b][hl];
            float gg = accs[0][3][hl][b] + accs[1][3][hl][b]
                     + accs[2][3][hl][b] + accs[3][3][hl][b] + xgs[3][b][hl];
            float c  = cs[hl][b];
            float iv = sigmoidf_(gi + Ps[0][hl] * c);
            float fv = sigmoidf_(gf + Ps[1][hl] * c);
            float ct = tanhf(gg);
            float cn = fv * c + iv * ct;
            float ov = sigmoidf_(go + Ps[2][hl] * cn);
            float hn = ov * tanhf(cn);
            if (t >= slen[b]) { hn = h0s[hl][b]; cn = c0s[hl][b]; }
            cs[hl][b] = cn;
            g_h[nxt][d][hb + hl][b] = __float2half(hn);
            out[(((size_t)t * 2 + d) * BSZ + b) * HID + hb + hl] = hn;
            if (s == SLEN - 1) {
                size_t fi = ((size_t)d * BSZ + b) * HID + hb + hl;
                Yh[fi] = hn;
                Yc[fi] = cn;
            }
        }
    }
}

// ---------------------------------------------------------------------------
extern "C" void kernel_launch(void* const* d_in, const int* in_sizes, int n_in,
                              void* d_out, int out_size) {
    const float* X   = (const float*)d_in[0];
    const float* W   = (const float*)d_in[1];
    const float* R   = (const float*)d_in[2];
    const float* Bb  = (const float*)d_in[3];
    const int*   sl  = (const int*)  d_in[4];
    const float* h0  = (const float*)d_in[5];
    const float* c0  = (const float*)d_in[6];
    const float* P   = (const float*)d_in[7];
    float* out = (float*)d_out;

    static int configured = 0;
    if (!configured) {
        cudaFuncSetAttribute(lstm_rec, cudaFuncAttributeMaxDynamicSharedMemorySize,
                             HS_BYTES);
        configured = 1;
    }

    gemm_xw_fp16<<<dim3(16, 256, 2), 256>>>(X, W, Bb);
    lstm_rec<<<NBLK, 512, HS_BYTES>>>(R, sl, h0, c0, P, out);
}